// round 14
// baseline (speedup 1.0000x reference)
#include <cuda_runtime.h>
#include <cuda_fp16.h>
#include <cstdint>

#define N_TOKENS 4096
#define D_IN     4096
#define D_HIDDEN 32768
#define TOPK     64
#define MARGIN   5e-3f
#define NBINS    4096

// ---------------- device scratch (no allocations allowed) -------------------
__device__ __half g_x1[(size_t)N_TOKENS * D_IN];
__device__ __half g_w1[(size_t)D_HIDDEN * D_IN];
__device__ __half g_wdecT[(size_t)D_HIDDEN * D_IN];   // fp16 transposed decoder
__device__ int   g_hist[(size_t)N_TOKENS * NBINS];    // 64MB per-token histograms
__device__ int   g_topk_idx[N_TOKENS * TOPK];
__device__ float g_topk_val[N_TOKENS * TOPK];
__device__ int   g_cand_idx[N_TOKENS * 64];
__device__ float g_cand_val[N_TOKENS * 64];
__device__ int   g_ndef[N_TOKENS];
__device__ int   g_ncand[N_TOKENS];

// ---------------- helpers ----------------------------------------------------
__device__ __forceinline__ uint32_t smem_u32(const void* p) {
    uint32_t a;
    asm("{ .reg .u64 t; cvta.to.shared.u64 t, %1; cvt.u32.u64 %0, t; }" : "=r"(a) : "l"(p));
    return a;
}
__device__ __forceinline__ void cp16(uint32_t saddr, const void* gaddr) {
    asm volatile("cp.async.cg.shared.global [%0], [%1], 16;" :: "r"(saddr), "l"(gaddr));
}
#define CP_COMMIT()  asm volatile("cp.async.commit_group;" ::: "memory")
#define CP_WAIT0()   asm volatile("cp.async.wait_group 0;" ::: "memory")
#define CP_WAIT1()   asm volatile("cp.async.wait_group 1;" ::: "memory")

#define LDSM_X4(d, addr) \
    asm volatile("ldmatrix.sync.aligned.m8n8.x4.shared.b16 {%0,%1,%2,%3}, [%4];" \
        : "=r"((d)[0]), "=r"((d)[1]), "=r"((d)[2]), "=r"((d)[3]) : "r"(addr))
#define LDSM_X2(d, addr) \
    asm volatile("ldmatrix.sync.aligned.m8n8.x2.shared.b16 {%0,%1}, [%2];" \
        : "=r"((d)[0]), "=r"((d)[1]) : "r"(addr))

__device__ __forceinline__ void mma16816(float* d, const uint32_t* a, const uint32_t* b) {
    asm volatile("mma.sync.aligned.m16n8k16.row.col.f32.f16.f16.f32 "
        "{%0,%1,%2,%3}, {%4,%5,%6,%7}, {%8,%9}, {%0,%1,%2,%3};"
        : "+f"(d[0]), "+f"(d[1]), "+f"(d[2]), "+f"(d[3])
        : "r"(a[0]), "r"(a[1]), "r"(a[2]), "r"(a[3]), "r"(b[0]), "r"(b[1]));
}

// histogram add (no return value -> RED)
__device__ __forceinline__ void hist_add(int row, float v) {
    if (v > 0.0f) {
        int b = (int)(v * 512.0f);
        if (b > NBINS - 1) b = NBINS - 1;
        atomicAdd(&g_hist[(size_t)row * NBINS + b], 1);
    }
}

// ---------------- zero histograms (graph replays on dirty state) ------------
__global__ __launch_bounds__(256)
void hist_zero_kernel()
{
    size_t i = ((size_t)blockIdx.x * 256 + threadIdx.x) * 4;
    *(int4*)(g_hist + i) = int4{0, 0, 0, 0};
}

// ---------------- convert kernels (fp32 -> fp16) ----------------------------
__global__ __launch_bounds__(256)
void split_x_kernel(const float* __restrict__ src)
{
    size_t i = ((size_t)blockIdx.x * 256 + threadIdx.x) * 4;
    if (i >= (size_t)N_TOKENS * D_IN) return;
    float4 v = *(const float4*)(src + i);
    *(__half2*)(g_x1 + i)     = __half2{__float2half_rn(v.x), __float2half_rn(v.y)};
    *(__half2*)(g_x1 + i + 2) = __half2{__float2half_rn(v.z), __float2half_rn(v.w)};
}

__global__ __launch_bounds__(256)
void split_w_kernel(const float* __restrict__ src)
{
    size_t i = ((size_t)blockIdx.x * 256 + threadIdx.x) * 4;
    if (i >= (size_t)D_HIDDEN * D_IN) return;
    float4 v = *(const float4*)(src + i);
    *(__half2*)(g_w1 + i)     = __half2{__float2half_rn(v.x), __float2half_rn(v.y)};
    *(__half2*)(g_w1 + i + 2) = __half2{__float2half_rn(v.z), __float2half_rn(v.w)};
}

// ---------------- encode: fp16 x*w GEMM on mma.sync (R7 mainloop verbatim) --
// CTA tile 128(tok) x 128(hid), BK=64, 8 warps 2x4, warp tile 64x32.
// 3-stage cp.async ring (96KB), 2 CTAs/SM. Epilogue additionally feeds the
// per-token top-k histograms via RED atomics (mainloop untouched).
#define EBK 64
#define ARR_BYTES 16384
#define STAGE_BYTES (2 * ARR_BYTES)      // 32KB
#define ENC_SMEM (3 * STAGE_BYTES)       // 96KB
#define N_STAGES (D_IN / EBK)            // 64

__global__ __launch_bounds__(256, 2)
void encode_mma_kernel(const float* __restrict__ bias, float* __restrict__ feat)
{
    extern __shared__ __align__(128) char smem[];
    const int tid  = threadIdx.x;
    const int wid  = tid >> 5;
    const int lane = tid & 31;
    const int wm   = wid >> 2;       // 0..1
    const int wn   = wid & 3;        // 0..3
    const int bn   = blockIdx.x * 128;   // token tile (fastest -> B tile L2-hot)
    const int bh   = blockIdx.y * 128;   // hidden tile
    const uint32_t smem_base = smem_u32(smem);

    float acc[4][4][4];
#pragma unroll
    for (int mt = 0; mt < 4; ++mt)
#pragma unroll
        for (int nt = 0; nt < 4; ++nt)
#pragma unroll
            for (int q = 0; q < 4; ++q) acc[mt][nt][q] = 0.0f;

#define PREFETCH(s) do {                                                          \
    const int _k0 = (s) * EBK;                                                    \
    const uint32_t _st = smem_base + ((s) % 3) * STAGE_BYTES;                     \
    _Pragma("unroll")                                                             \
    for (int _l = 0; _l < 4; ++_l) {                                              \
        int _id = _l * 256 + tid;                                                 \
        int _r = _id >> 3, _c = _id & 7;                                          \
        uint32_t _sw = (uint32_t)(_r * 128 + ((_c ^ (_r & 7)) << 4));             \
        size_t _ga = (size_t)(bn + _r) * D_IN + _k0 + _c * 8;                     \
        size_t _gb = (size_t)(bh + _r) * D_IN + _k0 + _c * 8;                     \
        cp16(_st + 0 * ARR_BYTES + _sw, g_x1 + _ga);                              \
        cp16(_st + 1 * ARR_BYTES + _sw, g_w1 + _gb);                              \
    }                                                                             \
    CP_COMMIT();                                                                  \
} while (0)

    PREFETCH(0);
    PREFETCH(1);

    const int rA_base = wm * 64 + (lane & 15);
    const int rB_base = wn * 32 + (lane & 7);

    for (int s = 0; s < N_STAGES; ++s) {
        if (s + 2 < N_STAGES) {
            CP_WAIT1();
            __syncthreads();
            PREFETCH(s + 2);
        } else {
            CP_WAIT0();
            __syncthreads();
        }
        const uint32_t st = smem_base + (s % 3) * STAGE_BYTES;

#pragma unroll
        for (int ks = 0; ks < 4; ++ks) {
            uint32_t a[4][4], b[4][2];
            const int cA = 2 * ks + (lane >> 4);
#pragma unroll
            for (int mt = 0; mt < 4; ++mt) {
                int r = rA_base + mt * 16;
                uint32_t off = st + (uint32_t)(r * 128 + ((cA ^ (r & 7)) << 4));
                LDSM_X4(a[mt], off);
            }
            const int cB = 2 * ks + ((lane >> 3) & 1);
#pragma unroll
            for (int nt = 0; nt < 4; ++nt) {
                int r = rB_base + nt * 8;
                uint32_t off = st + ARR_BYTES + (uint32_t)(r * 128 + ((cB ^ (r & 7)) << 4));
                LDSM_X2(b[nt], off);
            }
#pragma unroll
            for (int mt = 0; mt < 4; ++mt)
#pragma unroll
                for (int nt = 0; nt < 4; ++nt)
                    mma16816(acc[mt][nt], a[mt], b[nt]);
        }
        __syncthreads();
    }
#undef PREFETCH

    // Epilogue: +bias, ReLU, store fp32, feed per-token histograms
#pragma unroll
    for (int mt = 0; mt < 4; ++mt) {
        const int row0 = bn + wm * 64 + mt * 16 + (lane >> 2);
#pragma unroll
        for (int nt = 0; nt < 4; ++nt) {
            const int col0 = bh + wn * 32 + nt * 8 + (lane & 3) * 2;
            const float bb0 = bias[col0], bb1 = bias[col0 + 1];
            float2 v0, v1;
            v0.x = acc[mt][nt][0] + bb0; v0.x = v0.x > 0.0f ? v0.x : 0.0f;
            v0.y = acc[mt][nt][1] + bb1; v0.y = v0.y > 0.0f ? v0.y : 0.0f;
            v1.x = acc[mt][nt][2] + bb0; v1.x = v1.x > 0.0f ? v1.x : 0.0f;
            v1.y = acc[mt][nt][3] + bb1; v1.y = v1.y > 0.0f ? v1.y : 0.0f;
            *(float2*)&feat[(size_t)row0 * D_HIDDEN + col0]       = v0;
            *(float2*)&feat[(size_t)(row0 + 8) * D_HIDDEN + col0] = v1;
            hist_add(row0,     v0.x);
            hist_add(row0,     v0.y);
            hist_add(row0 + 8, v1.x);
            hist_add(row0 + 8, v1.y);
        }
    }
}

// ---------------- top-k: load prebuilt histogram + margin classify ----------
__global__ __launch_bounds__(256)
void topk_kernel(float* __restrict__ feat)
{
    const int n   = blockIdx.x;
    const int tid = threadIdx.x;
    float* row = feat + (size_t)n * D_HIDDEN;

    __shared__ int hist[NBINS];
    __shared__ int s_part[256];
    __shared__ int s_bin;
    __shared__ int s_ndef, s_ncand;

    // Load the histogram built by the encode epilogue (16KB)
    for (int i = tid * 4; i < NBINS; i += 1024)
        *(int4*)&hist[i] = *(const int4*)&g_hist[(size_t)n * NBINS + i];
    if (tid == 0) { s_bin = 0; s_ndef = 0; s_ncand = 0; }
    __syncthreads();

    const int hi_b = NBINS - 1 - tid * 16;
    int part = 0;
#pragma unroll
    for (int j = 0; j < 16; ++j) part += hist[hi_b - j];
    s_part[tid] = part;
    __syncthreads();
    for (int off = 1; off < 256; off <<= 1) {
        int v2 = (tid >= off) ? s_part[tid - off] : 0;
        __syncthreads();
        s_part[tid] += v2;
        __syncthreads();
    }
    const int incl = s_part[tid];
    const int excl = incl - part;
    if (excl < TOPK && incl >= TOPK) {
        int cum = excl;
        for (int j = 0; j < 16; ++j) {
            cum += hist[hi_b - j];
            if (cum >= TOPK) { s_bin = hi_b - j; break; }
        }
    }
    __syncthreads();

    const float lo = (float)s_bin / 512.0f - MARGIN;
    const float hi = (float)(s_bin + 1) / 512.0f + MARGIN;

    for (int i = tid; i < D_HIDDEN; i += 256) {
        float v = row[i];
        if (v > hi) {
            int p = atomicAdd(&s_ndef, 1);
            g_topk_idx[n * TOPK + p] = i;
            g_topk_val[n * TOPK + p] = v;
        } else {
            if (v >= lo) {
                int q = atomicAdd(&s_ncand, 1);
                if (q < 64) { g_cand_idx[n * 64 + q] = i; g_cand_val[n * 64 + q] = v; }
            }
            row[i] = 0.0f;
        }
    }
    __syncthreads();
    if (tid == 0) {
        g_ndef[n]  = s_ndef;
        g_ncand[n] = s_ncand < 64 ? s_ncand : 64;
    }
}

// ---------------- rerank: exact fp64 scoring of boundary candidates ---------
__global__ __launch_bounds__(256)
void rerank_kernel(const float* __restrict__ x, const float* __restrict__ W_enc,
                   const float* __restrict__ b_enc, float* __restrict__ feat)
{
    __shared__ float  sx[D_IN];
    __shared__ double sred[256];
    __shared__ double s_exact[64];

    const int n   = blockIdx.x;
    const int tid = threadIdx.x;
    const int ndef  = g_ndef[n];
    const int ncand = g_ncand[n];
    const int need  = TOPK - ndef;
    float* row = feat + (size_t)n * D_HIDDEN;

    if (need <= 0) return;

    if (ncand <= need) {
        for (int c = tid; c < ncand; c += 256) {
            int idx = g_cand_idx[n * 64 + c];
            float v = g_cand_val[n * 64 + c];
            row[idx] = v;
            g_topk_idx[n * TOPK + ndef + c] = idx;
            g_topk_val[n * TOPK + ndef + c] = v;
        }
        return;
    }

    for (int i = tid * 4; i < D_IN; i += 1024)
        *(float4*)&sx[i] = *(const float4*)(x + (size_t)n * D_IN + i);
    __syncthreads();

    for (int c = 0; c < ncand; ++c) {
        const float* w = W_enc + (size_t)g_cand_idx[n * 64 + c] * D_IN;
        double acc = 0.0;
        for (int j = tid; j < D_IN; j += 256)
            acc += (double)sx[j] * (double)w[j];
        sred[tid] = acc;
        __syncthreads();
        for (int st = 128; st > 0; st >>= 1) {
            if (tid < st) sred[tid] += sred[tid + st];
            __syncthreads();
        }
        if (tid == 0) {
            double v = sred[0] + (double)b_enc[g_cand_idx[n * 64 + c]];
            s_exact[c] = v > 0.0 ? v : 0.0;
        }
        __syncthreads();
    }

    if (tid == 0) {
        bool used[64];
        for (int c = 0; c < ncand; ++c) used[c] = false;
        for (int r = 0; r < need; ++r) {
            int best = -1;
            for (int c = 0; c < ncand; ++c) {
                if (used[c]) continue;
                if (best < 0 || s_exact[c] > s_exact[best] ||
                    (s_exact[c] == s_exact[best] &&
                     g_cand_idx[n * 64 + c] < g_cand_idx[n * 64 + best]))
                    best = c;
            }
            used[best] = true;
            int idx = g_cand_idx[n * 64 + best];
            float v = g_cand_val[n * 64 + best];
            row[idx] = v;
            g_topk_idx[n * TOPK + ndef + r] = idx;
            g_topk_val[n * TOPK + ndef + r] = v;
        }
    }
}

// ---------------- transpose W_dec [d][h] -> g_wdecT fp16 [h][d] -------------
__global__ __launch_bounds__(256)
void transpose_kernel(const float* __restrict__ W)
{
    __shared__ float t[32][65];     // [h][d]
    const int h0 = blockIdx.x * 32;
    const int d0 = blockIdx.y * 64;
    const int tx = threadIdx.x;     // 0..31
    const int ty = threadIdx.y;     // 0..7

#pragma unroll
    for (int i = 0; i < 64; i += 8)
        t[tx][i + ty] = W[(size_t)(d0 + i + ty) * D_HIDDEN + h0 + tx];
    __syncthreads();
#pragma unroll
    for (int i = 0; i < 32; i += 8) {
        const int h = i + ty;
        __half2 hv = __half2{__float2half_rn(t[h][2 * tx]),
                             __float2half_rn(t[h][2 * tx + 1])};
        *(__half2*)(g_wdecT + (size_t)(h0 + h) * D_IN + d0 + 2 * tx) = hv;
    }
}

// ---------------- sparse decode (fp16 weights, fp32 accum) ------------------
__global__ __launch_bounds__(256)
void decode_kernel(float* __restrict__ recon, const float* __restrict__ b_dec)
{
    const int n   = blockIdx.x;
    const int tid = threadIdx.x;

    __shared__ int   s_idx[TOPK];
    __shared__ float s_val[TOPK];
    if (tid < TOPK) {
        s_idx[tid] = g_topk_idx[n * TOPK + tid];
        s_val[tid] = g_topk_val[n * TOPK + tid];
    }
    __syncthreads();

    float acc[16];
#pragma unroll
    for (int r = 0; r < 8; ++r) {
        float2 b = *(const float2*)(b_dec + 2 * (tid + r * 256));
        acc[2 * r] = b.x; acc[2 * r + 1] = b.y;
    }

    for (int j = 0; j < TOPK; ++j) {
        const __half2* wr = (const __half2*)(g_wdecT + (size_t)s_idx[j] * D_IN);
        const float v = s_val[j];
#pragma unroll
        for (int r = 0; r < 8; ++r) {
            float2 w = __half22float2(wr[tid + r * 256]);
            acc[2 * r]     += v * w.x;
            acc[2 * r + 1] += v * w.y;
        }
    }

    float* out = recon + (size_t)n * D_IN;
#pragma unroll
    for (int r = 0; r < 8; ++r) {
        float2 o; o.x = acc[2 * r]; o.y = acc[2 * r + 1];
        *(float2*)(out + 2 * (tid + r * 256)) = o;
    }
}

// ---------------- launch -----------------------------------------------------
extern "C" void kernel_launch(void* const* d_in, const int* in_sizes, int n_in,
                              void* d_out, int out_size)
{
    const float* x     = (const float*)d_in[0];
    const float* W_enc = (const float*)d_in[1];
    const float* b_enc = (const float*)d_in[2];
    const float* W_dec = (const float*)d_in[3];
    const float* b_dec = (const float*)d_in[4];

    float* recon = (float*)d_out;
    float* feat  = (float*)d_out + (size_t)N_TOKENS * D_IN;

    cudaFuncSetAttribute(encode_mma_kernel,
                         cudaFuncAttributeMaxDynamicSharedMemorySize, ENC_SMEM);

    hist_zero_kernel<<<((size_t)N_TOKENS * NBINS) / 1024, 256>>>();
    split_x_kernel<<<(N_TOKENS * D_IN) / 1024, 256>>>(x);
    split_w_kernel<<<((size_t)D_HIDDEN * D_IN) / 1024, 256>>>(W_enc);
    transpose_kernel<<<dim3(D_HIDDEN / 32, D_IN / 64), dim3(32, 8)>>>(W_dec);

    encode_mma_kernel<<<dim3(N_TOKENS / 128, D_HIDDEN / 128), 256, ENC_SMEM>>>(b_enc, feat);

    topk_kernel<<<N_TOKENS, 256>>>(feat);
    rerank_kernel<<<N_TOKENS, 256>>>(x, W_enc, b_enc, feat);
    decode_kernel<<<N_TOKENS, 256>>>(recon, b_dec);
}

// round 15
// speedup vs baseline: 1.0211x; 1.0211x over previous
#include <cuda_runtime.h>
#include <cuda_fp16.h>
#include <cstdint>

#define N_TOKENS 4096
#define D_IN     4096
#define D_HIDDEN 32768
#define TOPK     64
#define MARGIN   5e-3f
#define NBINS    4096

// ---------------- device scratch (no allocations allowed) -------------------
__device__ __half g_x1[(size_t)N_TOKENS * D_IN];
__device__ __half g_w1[(size_t)D_HIDDEN * D_IN];
__device__ __half g_wdecT[(size_t)D_HIDDEN * D_IN];   // fp16 transposed decoder
__device__ int   g_topk_idx[N_TOKENS * TOPK];
__device__ float g_topk_val[N_TOKENS * TOPK];
__device__ int   g_cand_idx[N_TOKENS * 64];
__device__ float g_cand_val[N_TOKENS * 64];
__device__ int   g_ndef[N_TOKENS];
__device__ int   g_ncand[N_TOKENS];

// ---------------- helpers ----------------------------------------------------
__device__ __forceinline__ uint32_t smem_u32(const void* p) {
    uint32_t a;
    asm("{ .reg .u64 t; cvta.to.shared.u64 t, %1; cvt.u32.u64 %0, t; }" : "=r"(a) : "l"(p));
    return a;
}
__device__ __forceinline__ void cp16(uint32_t saddr, const void* gaddr) {
    asm volatile("cp.async.cg.shared.global [%0], [%1], 16;" :: "r"(saddr), "l"(gaddr));
}
#define CP_COMMIT()  asm volatile("cp.async.commit_group;" ::: "memory")
#define CP_WAIT0()   asm volatile("cp.async.wait_group 0;" ::: "memory")
#define CP_WAIT1()   asm volatile("cp.async.wait_group 1;" ::: "memory")

#define LDSM_X4(d, addr) \
    asm volatile("ldmatrix.sync.aligned.m8n8.x4.shared.b16 {%0,%1,%2,%3}, [%4];" \
        : "=r"((d)[0]), "=r"((d)[1]), "=r"((d)[2]), "=r"((d)[3]) : "r"(addr))
#define LDSM_X2(d, addr) \
    asm volatile("ldmatrix.sync.aligned.m8n8.x2.shared.b16 {%0,%1}, [%2];" \
        : "=r"((d)[0]), "=r"((d)[1]) : "r"(addr))

__device__ __forceinline__ void mma16816(float* d, const uint32_t* a, const uint32_t* b) {
    asm volatile("mma.sync.aligned.m16n8k16.row.col.f32.f16.f16.f32 "
        "{%0,%1,%2,%3}, {%4,%5,%6,%7}, {%8,%9}, {%0,%1,%2,%3};"
        : "+f"(d[0]), "+f"(d[1]), "+f"(d[2]), "+f"(d[3])
        : "r"(a[0]), "r"(a[1]), "r"(a[2]), "r"(a[3]), "r"(b[0]), "r"(b[1]));
}

// ---------------- convert kernels (fp32 -> fp16) ----------------------------
__global__ __launch_bounds__(256)
void split_x_kernel(const float* __restrict__ src)
{
    size_t i = ((size_t)blockIdx.x * 256 + threadIdx.x) * 4;
    if (i >= (size_t)N_TOKENS * D_IN) return;
    float4 v = *(const float4*)(src + i);
    *(__half2*)(g_x1 + i)     = __half2{__float2half_rn(v.x), __float2half_rn(v.y)};
    *(__half2*)(g_x1 + i + 2) = __half2{__float2half_rn(v.z), __float2half_rn(v.w)};
}

__global__ __launch_bounds__(256)
void split_w_kernel(const float* __restrict__ src)
{
    size_t i = ((size_t)blockIdx.x * 256 + threadIdx.x) * 4;
    if (i >= (size_t)D_HIDDEN * D_IN) return;
    float4 v = *(const float4*)(src + i);
    *(__half2*)(g_w1 + i)     = __half2{__float2half_rn(v.x), __float2half_rn(v.y)};
    *(__half2*)(g_w1 + i + 2) = __half2{__float2half_rn(v.z), __float2half_rn(v.w)};
}

// ---------------- encode: fp16 x*w GEMM on mma.sync (R7/R13 verbatim) -------
#define EBK 64
#define ARR_BYTES 16384
#define STAGE_BYTES (2 * ARR_BYTES)      // 32KB
#define ENC_SMEM (3 * STAGE_BYTES)       // 96KB
#define N_STAGES (D_IN / EBK)            // 64

__global__ __launch_bounds__(256, 2)
void encode_mma_kernel(const float* __restrict__ bias, float* __restrict__ feat)
{
    extern __shared__ __align__(128) char smem[];
    const int tid  = threadIdx.x;
    const int wid  = tid >> 5;
    const int lane = tid & 31;
    const int wm   = wid >> 2;       // 0..1
    const int wn   = wid & 3;        // 0..3
    const int bn   = blockIdx.x * 128;
    const int bh   = blockIdx.y * 128;
    const uint32_t smem_base = smem_u32(smem);

    float acc[4][4][4];
#pragma unroll
    for (int mt = 0; mt < 4; ++mt)
#pragma unroll
        for (int nt = 0; nt < 4; ++nt)
#pragma unroll
            for (int q = 0; q < 4; ++q) acc[mt][nt][q] = 0.0f;

#define PREFETCH(s) do {                                                          \
    const int _k0 = (s) * EBK;                                                    \
    const uint32_t _st = smem_base + ((s) % 3) * STAGE_BYTES;                     \
    _Pragma("unroll")                                                             \
    for (int _l = 0; _l < 4; ++_l) {                                              \
        int _id = _l * 256 + tid;                                                 \
        int _r = _id >> 3, _c = _id & 7;                                          \
        uint32_t _sw = (uint32_t)(_r * 128 + ((_c ^ (_r & 7)) << 4));             \
        size_t _ga = (size_t)(bn + _r) * D_IN + _k0 + _c * 8;                     \
        size_t _gb = (size_t)(bh + _r) * D_IN + _k0 + _c * 8;                     \
        cp16(_st + 0 * ARR_BYTES + _sw, g_x1 + _ga);                              \
        cp16(_st + 1 * ARR_BYTES + _sw, g_w1 + _gb);                              \
    }                                                                             \
    CP_COMMIT();                                                                  \
} while (0)

    PREFETCH(0);
    PREFETCH(1);

    const int rA_base = wm * 64 + (lane & 15);
    const int rB_base = wn * 32 + (lane & 7);

    for (int s = 0; s < N_STAGES; ++s) {
        if (s + 2 < N_STAGES) {
            CP_WAIT1();
            __syncthreads();
            PREFETCH(s + 2);
        } else {
            CP_WAIT0();
            __syncthreads();
        }
        const uint32_t st = smem_base + (s % 3) * STAGE_BYTES;

#pragma unroll
        for (int ks = 0; ks < 4; ++ks) {
            uint32_t a[4][4], b[4][2];
            const int cA = 2 * ks + (lane >> 4);
#pragma unroll
            for (int mt = 0; mt < 4; ++mt) {
                int r = rA_base + mt * 16;
                uint32_t off = st + (uint32_t)(r * 128 + ((cA ^ (r & 7)) << 4));
                LDSM_X4(a[mt], off);
            }
            const int cB = 2 * ks + ((lane >> 3) & 1);
#pragma unroll
            for (int nt = 0; nt < 4; ++nt) {
                int r = rB_base + nt * 8;
                uint32_t off = st + ARR_BYTES + (uint32_t)(r * 128 + ((cB ^ (r & 7)) << 4));
                LDSM_X2(b[nt], off);
            }
#pragma unroll
            for (int mt = 0; mt < 4; ++mt)
#pragma unroll
                for (int nt = 0; nt < 4; ++nt)
                    mma16816(acc[mt][nt], a[mt], b[nt]);
        }
        __syncthreads();
    }
#undef PREFETCH

    // Epilogue: +bias, ReLU, store fp32
#pragma unroll
    for (int mt = 0; mt < 4; ++mt) {
        const int row0 = bn + wm * 64 + mt * 16 + (lane >> 2);
#pragma unroll
        for (int nt = 0; nt < 4; ++nt) {
            const int col0 = bh + wn * 32 + nt * 8 + (lane & 3) * 2;
            const float bb0 = bias[col0], bb1 = bias[col0 + 1];
            float2 v0, v1;
            v0.x = acc[mt][nt][0] + bb0; v0.x = v0.x > 0.0f ? v0.x : 0.0f;
            v0.y = acc[mt][nt][1] + bb1; v0.y = v0.y > 0.0f ? v0.y : 0.0f;
            v1.x = acc[mt][nt][2] + bb0; v1.x = v1.x > 0.0f ? v1.x : 0.0f;
            v1.y = acc[mt][nt][3] + bb1; v1.y = v1.y > 0.0f ? v1.y : 0.0f;
            *(float2*)&feat[(size_t)row0 * D_HIDDEN + col0]       = v0;
            *(float2*)&feat[(size_t)(row0 + 8) * D_HIDDEN + col0] = v1;
        }
    }
}

// ---------------- top-k: smem-cached row, 1 global read + 1 write -----------
// Row (128KB) cached in dynamic smem during histogram pass; classify from smem.
#define TOPK_SMEM (D_HIDDEN * 4 + NBINS * 4)    // 144KB

__global__ __launch_bounds__(512)
void topk_kernel(float* __restrict__ feat)
{
    extern __shared__ char tsm[];
    float* srow = (float*)tsm;
    int*   hist = (int*)(tsm + D_HIDDEN * 4);

    __shared__ int s_part[512];
    __shared__ int s_bin, s_ndef, s_ncand;

    const int n   = blockIdx.x;
    const int tid = threadIdx.x;
    float* row = feat + (size_t)n * D_HIDDEN;

    for (int i = tid; i < NBINS; i += 512) hist[i] = 0;
    if (tid == 0) { s_bin = 0; s_ndef = 0; s_ncand = 0; }
    __syncthreads();

    // Load row into smem + build histogram
    for (int i = tid * 4; i < D_HIDDEN; i += 2048) {
        float4 v = *(const float4*)(row + i);
        *(float4*)&srow[i] = v;
        float f[4] = {v.x, v.y, v.z, v.w};
#pragma unroll
        for (int j = 0; j < 4; ++j) {
            if (f[j] > 0.0f) {
                int b = (int)(f[j] * 512.0f);
                if (b > NBINS - 1) b = NBINS - 1;
                atomicAdd(&hist[b], 1);
            }
        }
    }
    __syncthreads();

    // suffix sums from the top: thread t covers bins [4095-8t-7, 4095-8t]
    const int hi_b = NBINS - 1 - tid * 8;
    int part = 0;
#pragma unroll
    for (int j = 0; j < 8; ++j) part += hist[hi_b - j];
    s_part[tid] = part;
    __syncthreads();
    for (int off = 1; off < 512; off <<= 1) {
        int v2 = (tid >= off) ? s_part[tid - off] : 0;
        __syncthreads();
        s_part[tid] += v2;
        __syncthreads();
    }
    const int incl = s_part[tid];
    const int excl = incl - part;
    if (excl < TOPK && incl >= TOPK) {
        int cum = excl;
        for (int j = 0; j < 8; ++j) {
            cum += hist[hi_b - j];
            if (cum >= TOPK) { s_bin = hi_b - j; break; }
        }
    }
    __syncthreads();

    const float lo = (float)s_bin / 512.0f - MARGIN;
    const float hi = (float)(s_bin + 1) / 512.0f + MARGIN;

    // Classify from smem, write masked row densely
    for (int i = tid * 4; i < D_HIDDEN; i += 2048) {
        float4 v = *(float4*)&srow[i];
        float f[4] = {v.x, v.y, v.z, v.w};
        float o[4];
#pragma unroll
        for (int j = 0; j < 4; ++j) {
            float vv = f[j];
            if (vv > hi) {
                int p = atomicAdd(&s_ndef, 1);
                g_topk_idx[n * TOPK + p] = i + j;
                g_topk_val[n * TOPK + p] = vv;
                o[j] = vv;
            } else {
                if (vv >= lo) {
                    int q = atomicAdd(&s_ncand, 1);
                    if (q < 64) { g_cand_idx[n * 64 + q] = i + j; g_cand_val[n * 64 + q] = vv; }
                }
                o[j] = 0.0f;
            }
        }
        float4 ov; ov.x = o[0]; ov.y = o[1]; ov.z = o[2]; ov.w = o[3];
        *(float4*)(row + i) = ov;
    }
    __syncthreads();
    if (tid == 0) {
        g_ndef[n]  = s_ndef;
        g_ncand[n] = s_ncand < 64 ? s_ncand : 64;
    }
}

// ---------------- rerank: exact fp64 scoring of boundary candidates ---------
__global__ __launch_bounds__(256)
void rerank_kernel(const float* __restrict__ x, const float* __restrict__ W_enc,
                   const float* __restrict__ b_enc, float* __restrict__ feat)
{
    __shared__ float  sx[D_IN];
    __shared__ double sred[256];
    __shared__ double s_exact[64];

    const int n   = blockIdx.x;
    const int tid = threadIdx.x;
    const int ndef  = g_ndef[n];
    const int ncand = g_ncand[n];
    const int need  = TOPK - ndef;
    float* row = feat + (size_t)n * D_HIDDEN;

    if (need <= 0) return;

    if (ncand <= need) {
        for (int c = tid; c < ncand; c += 256) {
            int idx = g_cand_idx[n * 64 + c];
            float v = g_cand_val[n * 64 + c];
            row[idx] = v;
            g_topk_idx[n * TOPK + ndef + c] = idx;
            g_topk_val[n * TOPK + ndef + c] = v;
        }
        return;
    }

    for (int i = tid * 4; i < D_IN; i += 1024)
        *(float4*)&sx[i] = *(const float4*)(x + (size_t)n * D_IN + i);
    __syncthreads();

    for (int c = 0; c < ncand; ++c) {
        const float* w = W_enc + (size_t)g_cand_idx[n * 64 + c] * D_IN;
        double acc = 0.0;
        for (int j = tid; j < D_IN; j += 256)
            acc += (double)sx[j] * (double)w[j];
        sred[tid] = acc;
        __syncthreads();
        for (int st = 128; st > 0; st >>= 1) {
            if (tid < st) sred[tid] += sred[tid + st];
            __syncthreads();
        }
        if (tid == 0) {
            double v = sred[0] + (double)b_enc[g_cand_idx[n * 64 + c]];
            s_exact[c] = v > 0.0 ? v : 0.0;
        }
        __syncthreads();
    }

    if (tid == 0) {
        bool used[64];
        for (int c = 0; c < ncand; ++c) used[c] = false;
        for (int r = 0; r < need; ++r) {
            int best = -1;
            for (int c = 0; c < ncand; ++c) {
                if (used[c]) continue;
                if (best < 0 || s_exact[c] > s_exact[best] ||
                    (s_exact[c] == s_exact[best] &&
                     g_cand_idx[n * 64 + c] < g_cand_idx[n * 64 + best]))
                    best = c;
            }
            used[best] = true;
            int idx = g_cand_idx[n * 64 + best];
            float v = g_cand_val[n * 64 + best];
            row[idx] = v;
            g_topk_idx[n * TOPK + ndef + r] = idx;
            g_topk_val[n * TOPK + ndef + r] = v;
        }
    }
}

// ---------------- transpose W_dec [d][h] -> g_wdecT fp16 [h][d] -------------
__global__ __launch_bounds__(256)
void transpose_kernel(const float* __restrict__ W)
{
    __shared__ float t[32][65];     // [h][d]
    const int h0 = blockIdx.x * 32;
    const int d0 = blockIdx.y * 64;
    const int tx = threadIdx.x;     // 0..31
    const int ty = threadIdx.y;     // 0..7

#pragma unroll
    for (int i = 0; i < 64; i += 8)
        t[tx][i + ty] = W[(size_t)(d0 + i + ty) * D_HIDDEN + h0 + tx];
    __syncthreads();
#pragma unroll
    for (int i = 0; i < 32; i += 8) {
        const int h = i + ty;
        __half2 hv = __half2{__float2half_rn(t[h][2 * tx]),
                             __float2half_rn(t[h][2 * tx + 1])};
        *(__half2*)(g_wdecT + (size_t)(h0 + h) * D_IN + d0 + 2 * tx) = hv;
    }
}

// ---------------- sparse decode (fp16 weights, fp32 accum) ------------------
__global__ __launch_bounds__(256)
void decode_kernel(float* __restrict__ recon, const float* __restrict__ b_dec)
{
    const int n   = blockIdx.x;
    const int tid = threadIdx.x;

    __shared__ int   s_idx[TOPK];
    __shared__ float s_val[TOPK];
    if (tid < TOPK) {
        s_idx[tid] = g_topk_idx[n * TOPK + tid];
        s_val[tid] = g_topk_val[n * TOPK + tid];
    }
    __syncthreads();

    float acc[16];
#pragma unroll
    for (int r = 0; r < 8; ++r) {
        float2 b = *(const float2*)(b_dec + 2 * (tid + r * 256));
        acc[2 * r] = b.x; acc[2 * r + 1] = b.y;
    }

    for (int j = 0; j < TOPK; ++j) {
        const __half2* wr = (const __half2*)(g_wdecT + (size_t)s_idx[j] * D_IN);
        const float v = s_val[j];
#pragma unroll
        for (int r = 0; r < 8; ++r) {
            float2 w = __half22float2(wr[tid + r * 256]);
            acc[2 * r]     += v * w.x;
            acc[2 * r + 1] += v * w.y;
        }
    }

    float* out = recon + (size_t)n * D_IN;
#pragma unroll
    for (int r = 0; r < 8; ++r) {
        float2 o; o.x = acc[2 * r]; o.y = acc[2 * r + 1];
        *(float2*)(out + 2 * (tid + r * 256)) = o;
    }
}

// ---------------- launch -----------------------------------------------------
extern "C" void kernel_launch(void* const* d_in, const int* in_sizes, int n_in,
                              void* d_out, int out_size)
{
    const float* x     = (const float*)d_in[0];
    const float* W_enc = (const float*)d_in[1];
    const float* b_enc = (const float*)d_in[2];
    const float* W_dec = (const float*)d_in[3];
    const float* b_dec = (const float*)d_in[4];

    float* recon = (float*)d_out;
    float* feat  = (float*)d_out + (size_t)N_TOKENS * D_IN;

    static bool s_init = false;
    static cudaStream_t s_side;
    static cudaEvent_t  s_fork, s_join;
    if (!s_init) {
        cudaStreamCreateWithFlags(&s_side, cudaStreamNonBlocking);
        cudaEventCreateWithFlags(&s_fork, cudaEventDisableTiming);
        cudaEventCreateWithFlags(&s_join, cudaEventDisableTiming);
        cudaFuncSetAttribute(encode_mma_kernel,
                             cudaFuncAttributeMaxDynamicSharedMemorySize, ENC_SMEM);
        cudaFuncSetAttribute(topk_kernel,
                             cudaFuncAttributeMaxDynamicSharedMemorySize, TOPK_SMEM);
        s_init = true;
    }

    // Fork: transpose on the side stream, overlapped with split/encode/topk.
    cudaEventRecord(s_fork, 0);
    cudaStreamWaitEvent(s_side, s_fork, 0);
    transpose_kernel<<<dim3(D_HIDDEN / 32, D_IN / 64), dim3(32, 8), 0, s_side>>>(W_dec);
    cudaEventRecord(s_join, s_side);

    // Main stream chain
    split_x_kernel<<<(N_TOKENS * D_IN) / 1024, 256>>>(x);
    split_w_kernel<<<((size_t)D_HIDDEN * D_IN) / 1024, 256>>>(W_enc);
    encode_mma_kernel<<<dim3(N_TOKENS / 128, D_HIDDEN / 128), 256, ENC_SMEM>>>(b_enc, feat);
    topk_kernel<<<N_TOKENS, 512, TOPK_SMEM>>>(feat);
    rerank_kernel<<<N_TOKENS, 256>>>(x, W_enc, b_enc, feat);

    // Join: decode needs g_wdecT from the side stream.
    cudaStreamWaitEvent(0, s_join, 0);
    decode_kernel<<<N_TOKENS, 256>>>(recon, b_dec);
}

// round 16
// speedup vs baseline: 1.0335x; 1.0121x over previous
#include <cuda_runtime.h>
#include <cuda_fp16.h>
#include <cstdint>

#define N_TOKENS 4096
#define D_IN     4096
#define D_HIDDEN 32768
#define TOPK     64
#define MARGIN   5e-3f
#define NBINS    4096

// ---------------- device scratch (no allocations allowed) -------------------
__device__ __half g_x1[(size_t)N_TOKENS * D_IN];
__device__ __half g_w1[(size_t)D_HIDDEN * D_IN];
__device__ __half g_wdecT[(size_t)D_HIDDEN * D_IN];   // fp16 transposed decoder
__device__ int   g_topk_idx[N_TOKENS * TOPK];
__device__ float g_topk_val[N_TOKENS * TOPK];
__device__ int   g_cand_idx[N_TOKENS * 64];
__device__ float g_cand_val[N_TOKENS * 64];
__device__ int   g_ndef[N_TOKENS];
__device__ int   g_ncand[N_TOKENS];

// ---------------- helpers ----------------------------------------------------
__device__ __forceinline__ uint32_t smem_u32(const void* p) {
    uint32_t a;
    asm("{ .reg .u64 t; cvta.to.shared.u64 t, %1; cvt.u32.u64 %0, t; }" : "=r"(a) : "l"(p));
    return a;
}
__device__ __forceinline__ void cp16(uint32_t saddr, const void* gaddr) {
    asm volatile("cp.async.cg.shared.global [%0], [%1], 16;" :: "r"(saddr), "l"(gaddr));
}
#define CP_COMMIT()  asm volatile("cp.async.commit_group;" ::: "memory")
#define CP_WAIT0()   asm volatile("cp.async.wait_group 0;" ::: "memory")
#define CP_WAIT1()   asm volatile("cp.async.wait_group 1;" ::: "memory")

#define LDSM_X4(d, addr) \
    asm volatile("ldmatrix.sync.aligned.m8n8.x4.shared.b16 {%0,%1,%2,%3}, [%4];" \
        : "=r"((d)[0]), "=r"((d)[1]), "=r"((d)[2]), "=r"((d)[3]) : "r"(addr))
#define LDSM_X2(d, addr) \
    asm volatile("ldmatrix.sync.aligned.m8n8.x2.shared.b16 {%0,%1}, [%2];" \
        : "=r"((d)[0]), "=r"((d)[1]) : "r"(addr))

__device__ __forceinline__ void mma16816(float* d, const uint32_t* a, const uint32_t* b) {
    asm volatile("mma.sync.aligned.m16n8k16.row.col.f32.f16.f16.f32 "
        "{%0,%1,%2,%3}, {%4,%5,%6,%7}, {%8,%9}, {%0,%1,%2,%3};"
        : "+f"(d[0]), "+f"(d[1]), "+f"(d[2]), "+f"(d[3])
        : "r"(a[0]), "r"(a[1]), "r"(a[2]), "r"(a[3]), "r"(b[0]), "r"(b[1]));
}

// ---------------- convert kernels (fp32 -> fp16) ----------------------------
__global__ __launch_bounds__(256)
void split_x_kernel(const float* __restrict__ src)
{
    size_t i = ((size_t)blockIdx.x * 256 + threadIdx.x) * 4;
    if (i >= (size_t)N_TOKENS * D_IN) return;
    float4 v = *(const float4*)(src + i);
    *(__half2*)(g_x1 + i)     = __half2{__float2half_rn(v.x), __float2half_rn(v.y)};
    *(__half2*)(g_x1 + i + 2) = __half2{__float2half_rn(v.z), __float2half_rn(v.w)};
}

__global__ __launch_bounds__(256)
void split_w_kernel(const float* __restrict__ src)
{
    size_t i = ((size_t)blockIdx.x * 256 + threadIdx.x) * 4;
    if (i >= (size_t)D_HIDDEN * D_IN) return;
    float4 v = *(const float4*)(src + i);
    *(__half2*)(g_w1 + i)     = __half2{__float2half_rn(v.x), __float2half_rn(v.y)};
    *(__half2*)(g_w1 + i + 2) = __half2{__float2half_rn(v.z), __float2half_rn(v.w)};
}

// ---------------- encode: fp16 x*w GEMM on mma.sync (R7/R13 verbatim) -------
#define EBK 64
#define ARR_BYTES 16384
#define STAGE_BYTES (2 * ARR_BYTES)      // 32KB
#define ENC_SMEM (3 * STAGE_BYTES)       // 96KB
#define N_STAGES (D_IN / EBK)            // 64

__global__ __launch_bounds__(256, 2)
void encode_mma_kernel(const float* __restrict__ bias, float* __restrict__ feat)
{
    extern __shared__ __align__(128) char smem[];
    const int tid  = threadIdx.x;
    const int wid  = tid >> 5;
    const int lane = tid & 31;
    const int wm   = wid >> 2;       // 0..1
    const int wn   = wid & 3;        // 0..3
    const int bn   = blockIdx.x * 128;
    const int bh   = blockIdx.y * 128;
    const uint32_t smem_base = smem_u32(smem);

    float acc[4][4][4];
#pragma unroll
    for (int mt = 0; mt < 4; ++mt)
#pragma unroll
        for (int nt = 0; nt < 4; ++nt)
#pragma unroll
            for (int q = 0; q < 4; ++q) acc[mt][nt][q] = 0.0f;

#define PREFETCH(s) do {                                                          \
    const int _k0 = (s) * EBK;                                                    \
    const uint32_t _st = smem_base + ((s) % 3) * STAGE_BYTES;                     \
    _Pragma("unroll")                                                             \
    for (int _l = 0; _l < 4; ++_l) {                                              \
        int _id = _l * 256 + tid;                                                 \
        int _r = _id >> 3, _c = _id & 7;                                          \
        uint32_t _sw = (uint32_t)(_r * 128 + ((_c ^ (_r & 7)) << 4));             \
        size_t _ga = (size_t)(bn + _r) * D_IN + _k0 + _c * 8;                     \
        size_t _gb = (size_t)(bh + _r) * D_IN + _k0 + _c * 8;                     \
        cp16(_st + 0 * ARR_BYTES + _sw, g_x1 + _ga);                              \
        cp16(_st + 1 * ARR_BYTES + _sw, g_w1 + _gb);                              \
    }                                                                             \
    CP_COMMIT();                                                                  \
} while (0)

    PREFETCH(0);
    PREFETCH(1);

    const int rA_base = wm * 64 + (lane & 15);
    const int rB_base = wn * 32 + (lane & 7);

    for (int s = 0; s < N_STAGES; ++s) {
        if (s + 2 < N_STAGES) {
            CP_WAIT1();
            __syncthreads();
            PREFETCH(s + 2);
        } else {
            CP_WAIT0();
            __syncthreads();
        }
        const uint32_t st = smem_base + (s % 3) * STAGE_BYTES;

#pragma unroll
        for (int ks = 0; ks < 4; ++ks) {
            uint32_t a[4][4], b[4][2];
            const int cA = 2 * ks + (lane >> 4);
#pragma unroll
            for (int mt = 0; mt < 4; ++mt) {
                int r = rA_base + mt * 16;
                uint32_t off = st + (uint32_t)(r * 128 + ((cA ^ (r & 7)) << 4));
                LDSM_X4(a[mt], off);
            }
            const int cB = 2 * ks + ((lane >> 3) & 1);
#pragma unroll
            for (int nt = 0; nt < 4; ++nt) {
                int r = rB_base + nt * 8;
                uint32_t off = st + ARR_BYTES + (uint32_t)(r * 128 + ((cB ^ (r & 7)) << 4));
                LDSM_X2(b[nt], off);
            }
#pragma unroll
            for (int mt = 0; mt < 4; ++mt)
#pragma unroll
                for (int nt = 0; nt < 4; ++nt)
                    mma16816(acc[mt][nt], a[mt], b[nt]);
        }
        __syncthreads();
    }
#undef PREFETCH

    // Epilogue: +bias, ReLU, store fp32
#pragma unroll
    for (int mt = 0; mt < 4; ++mt) {
        const int row0 = bn + wm * 64 + mt * 16 + (lane >> 2);
#pragma unroll
        for (int nt = 0; nt < 4; ++nt) {
            const int col0 = bh + wn * 32 + nt * 8 + (lane & 3) * 2;
            const float bb0 = bias[col0], bb1 = bias[col0 + 1];
            float2 v0, v1;
            v0.x = acc[mt][nt][0] + bb0; v0.x = v0.x > 0.0f ? v0.x : 0.0f;
            v0.y = acc[mt][nt][1] + bb1; v0.y = v0.y > 0.0f ? v0.y : 0.0f;
            v1.x = acc[mt][nt][2] + bb0; v1.x = v1.x > 0.0f ? v1.x : 0.0f;
            v1.y = acc[mt][nt][3] + bb1; v1.y = v1.y > 0.0f ? v1.y : 0.0f;
            *(float2*)&feat[(size_t)row0 * D_HIDDEN + col0]       = v0;
            *(float2*)&feat[(size_t)(row0 + 8) * D_HIDDEN + col0] = v1;
        }
    }
}

// ---------------- top-k: 1-pass linear histogram + margin classify (R13) ----
__global__ __launch_bounds__(256)
void topk_kernel(float* __restrict__ feat)
{
    const int n   = blockIdx.x;
    const int tid = threadIdx.x;
    float* row = feat + (size_t)n * D_HIDDEN;

    __shared__ int hist[NBINS];
    __shared__ int s_part[256];
    __shared__ int s_bin;
    __shared__ int s_ndef, s_ncand;

    for (int i = tid; i < NBINS; i += 256) hist[i] = 0;
    if (tid == 0) { s_bin = 0; s_ndef = 0; s_ncand = 0; }
    __syncthreads();

    for (int i = tid; i < D_HIDDEN; i += 256) {
        float v = row[i];
        if (v > 0.0f) {
            int b = (int)(v * 512.0f);
            if (b > NBINS - 1) b = NBINS - 1;
            atomicAdd(&hist[b], 1);
        }
    }
    __syncthreads();

    const int hi_b = NBINS - 1 - tid * 16;
    int part = 0;
#pragma unroll
    for (int j = 0; j < 16; ++j) part += hist[hi_b - j];
    s_part[tid] = part;
    __syncthreads();
    for (int off = 1; off < 256; off <<= 1) {
        int v2 = (tid >= off) ? s_part[tid - off] : 0;
        __syncthreads();
        s_part[tid] += v2;
        __syncthreads();
    }
    const int incl = s_part[tid];
    const int excl = incl - part;
    if (excl < TOPK && incl >= TOPK) {
        int cum = excl;
        for (int j = 0; j < 16; ++j) {
            cum += hist[hi_b - j];
            if (cum >= TOPK) { s_bin = hi_b - j; break; }
        }
    }
    __syncthreads();

    const float lo = (float)s_bin / 512.0f - MARGIN;
    const float hi = (float)(s_bin + 1) / 512.0f + MARGIN;

    for (int i = tid; i < D_HIDDEN; i += 256) {
        float v = row[i];
        if (v > hi) {
            int p = atomicAdd(&s_ndef, 1);
            g_topk_idx[n * TOPK + p] = i;
            g_topk_val[n * TOPK + p] = v;
        } else {
            if (v >= lo) {
                int q = atomicAdd(&s_ncand, 1);
                if (q < 64) { g_cand_idx[n * 64 + q] = i; g_cand_val[n * 64 + q] = v; }
            }
            row[i] = 0.0f;
        }
    }
    __syncthreads();
    if (tid == 0) {
        g_ndef[n]  = s_ndef;
        g_ncand[n] = s_ncand < 64 ? s_ncand : 64;
    }
}

// ---------------- rerank: exact fp64 scoring of boundary candidates ---------
__global__ __launch_bounds__(256)
void rerank_kernel(const float* __restrict__ x, const float* __restrict__ W_enc,
                   const float* __restrict__ b_enc, float* __restrict__ feat)
{
    __shared__ float  sx[D_IN];
    __shared__ double sred[256];
    __shared__ double s_exact[64];

    const int n   = blockIdx.x;
    const int tid = threadIdx.x;
    const int ndef  = g_ndef[n];
    const int ncand = g_ncand[n];
    const int need  = TOPK - ndef;
    float* row = feat + (size_t)n * D_HIDDEN;

    if (need <= 0) return;

    if (ncand <= need) {
        for (int c = tid; c < ncand; c += 256) {
            int idx = g_cand_idx[n * 64 + c];
            float v = g_cand_val[n * 64 + c];
            row[idx] = v;
            g_topk_idx[n * TOPK + ndef + c] = idx;
            g_topk_val[n * TOPK + ndef + c] = v;
        }
        return;
    }

    for (int i = tid * 4; i < D_IN; i += 1024)
        *(float4*)&sx[i] = *(const float4*)(x + (size_t)n * D_IN + i);
    __syncthreads();

    for (int c = 0; c < ncand; ++c) {
        const float* w = W_enc + (size_t)g_cand_idx[n * 64 + c] * D_IN;
        double acc = 0.0;
        for (int j = tid; j < D_IN; j += 256)
            acc += (double)sx[j] * (double)w[j];
        sred[tid] = acc;
        __syncthreads();
        for (int st = 128; st > 0; st >>= 1) {
            if (tid < st) sred[tid] += sred[tid + st];
            __syncthreads();
        }
        if (tid == 0) {
            double v = sred[0] + (double)b_enc[g_cand_idx[n * 64 + c]];
            s_exact[c] = v > 0.0 ? v : 0.0;
        }
        __syncthreads();
    }

    if (tid == 0) {
        bool used[64];
        for (int c = 0; c < ncand; ++c) used[c] = false;
        for (int r = 0; r < need; ++r) {
            int best = -1;
            for (int c = 0; c < ncand; ++c) {
                if (used[c]) continue;
                if (best < 0 || s_exact[c] > s_exact[best] ||
                    (s_exact[c] == s_exact[best] &&
                     g_cand_idx[n * 64 + c] < g_cand_idx[n * 64 + best]))
                    best = c;
            }
            used[best] = true;
            int idx = g_cand_idx[n * 64 + best];
            float v = g_cand_val[n * 64 + best];
            row[idx] = v;
            g_topk_idx[n * TOPK + ndef + r] = idx;
            g_topk_val[n * TOPK + ndef + r] = v;
        }
    }
}

// ---------------- transpose W_dec [d][h] -> g_wdecT fp16 [h][d] -------------
__global__ __launch_bounds__(256)
void transpose_kernel(const float* __restrict__ W)
{
    __shared__ float t[32][65];     // [h][d]
    const int h0 = blockIdx.x * 32;
    const int d0 = blockIdx.y * 64;
    const int tx = threadIdx.x;     // 0..31
    const int ty = threadIdx.y;     // 0..7

#pragma unroll
    for (int i = 0; i < 64; i += 8)
        t[tx][i + ty] = W[(size_t)(d0 + i + ty) * D_HIDDEN + h0 + tx];
    __syncthreads();
#pragma unroll
    for (int i = 0; i < 32; i += 8) {
        const int h = i + ty;
        __half2 hv = __half2{__float2half_rn(t[h][2 * tx]),
                             __float2half_rn(t[h][2 * tx + 1])};
        *(__half2*)(g_wdecT + (size_t)(h0 + h) * D_IN + d0 + 2 * tx) = hv;
    }
}

// ---------------- sparse decode (fp16 weights, fp32 accum) ------------------
__global__ __launch_bounds__(256)
void decode_kernel(float* __restrict__ recon, const float* __restrict__ b_dec)
{
    const int n   = blockIdx.x;
    const int tid = threadIdx.x;

    __shared__ int   s_idx[TOPK];
    __shared__ float s_val[TOPK];
    if (tid < TOPK) {
        s_idx[tid] = g_topk_idx[n * TOPK + tid];
        s_val[tid] = g_topk_val[n * TOPK + tid];
    }
    __syncthreads();

    float acc[16];
#pragma unroll
    for (int r = 0; r < 8; ++r) {
        float2 b = *(const float2*)(b_dec + 2 * (tid + r * 256));
        acc[2 * r] = b.x; acc[2 * r + 1] = b.y;
    }

    for (int j = 0; j < TOPK; ++j) {
        const __half2* wr = (const __half2*)(g_wdecT + (size_t)s_idx[j] * D_IN);
        const float v = s_val[j];
#pragma unroll
        for (int r = 0; r < 8; ++r) {
            float2 w = __half22float2(wr[tid + r * 256]);
            acc[2 * r]     += v * w.x;
            acc[2 * r + 1] += v * w.y;
        }
    }

    float* out = recon + (size_t)n * D_IN;
#pragma unroll
    for (int r = 0; r < 8; ++r) {
        float2 o; o.x = acc[2 * r]; o.y = acc[2 * r + 1];
        *(float2*)(out + 2 * (tid + r * 256)) = o;
    }
}

// ---------------- launch -----------------------------------------------------
extern "C" void kernel_launch(void* const* d_in, const int* in_sizes, int n_in,
                              void* d_out, int out_size)
{
    const float* x     = (const float*)d_in[0];
    const float* W_enc = (const float*)d_in[1];
    const float* b_enc = (const float*)d_in[2];
    const float* W_dec = (const float*)d_in[3];
    const float* b_dec = (const float*)d_in[4];

    float* recon = (float*)d_out;
    float* feat  = (float*)d_out + (size_t)N_TOKENS * D_IN;

    static bool s_init = false;
    static cudaStream_t s_side;
    static cudaEvent_t  s_fork, s_join;
    if (!s_init) {
        cudaStreamCreateWithFlags(&s_side, cudaStreamNonBlocking);
        cudaEventCreateWithFlags(&s_fork, cudaEventDisableTiming);
        cudaEventCreateWithFlags(&s_join, cudaEventDisableTiming);
        cudaFuncSetAttribute(encode_mma_kernel,
                             cudaFuncAttributeMaxDynamicSharedMemorySize, ENC_SMEM);
        s_init = true;
    }

    // Main stream: splits first (DRAM-bound, run alone).
    split_x_kernel<<<(N_TOKENS * D_IN) / 1024, 256>>>(x);
    split_w_kernel<<<((size_t)D_HIDDEN * D_IN) / 1024, 256>>>(W_enc);

    // Fork AFTER splits: transpose runs concurrently with the compute-bound
    // encode (DRAM 4.3% idle there), not with the DRAM-bound splits.
    cudaEventRecord(s_fork, 0);
    cudaStreamWaitEvent(s_side, s_fork, 0);
    transpose_kernel<<<dim3(D_HIDDEN / 32, D_IN / 64), dim3(32, 8), 0, s_side>>>(W_dec);
    cudaEventRecord(s_join, s_side);

    encode_mma_kernel<<<dim3(N_TOKENS / 128, D_HIDDEN / 128), 256, ENC_SMEM>>>(b_enc, feat);
    topk_kernel<<<N_TOKENS, 256>>>(feat);
    rerank_kernel<<<N_TOKENS, 256>>>(x, W_enc, b_enc, feat);

    // Join: decode needs g_wdecT from the side stream.
    cudaStreamWaitEvent(0, s_join, 0);
    decode_kernel<<<N_TOKENS, 256>>>(recon, b_dec);
}